// round 3
// baseline (speedup 1.0000x reference)
#include <cuda_runtime.h>
#include <math.h>
#include <stdint.h>

// Problem constants
#define BB   4
#define TT   2048
#define CC   1024
#define NH   16
#define DD   64
#define MROWS (BB*TT)                      // 8192
#define OUT_ELEMS ((size_t)BB*TT*CC)       // 8388608

// Scratch (device globals — no allocation allowed)
__device__ float g_x[(size_t)MROWS*CC];            // tf32-rounded x
__device__ float g_wt[4*(size_t)CC*CC];            // W^T, tf32-rounded (q,k,v,o)
__device__ float g_q[(size_t)BB*NH*TT*DD];         // [bn][t][d]
__device__ float g_k[(size_t)BB*NH*TT*DD];         // [bn][t][d]
__device__ float g_v[(size_t)BB*NH*TT*DD];         // [bn][d][t]  (transposed)
__device__ float g_attn[(size_t)MROWS*CC];         // [b][t][n*64+d]

// ---------------------------------------------------------------------------
// PTX helpers
// ---------------------------------------------------------------------------
__device__ __forceinline__ uint32_t smem_u32(const void* p) {
    return (uint32_t)__cvta_generic_to_shared(p);
}
__device__ __forceinline__ float tf32r(float x) {
    uint32_t u;
    asm("cvt.rna.tf32.f32 %0, %1;" : "=r"(u) : "f"(x));
    return __uint_as_float(u);
}
__device__ __forceinline__ void ldsm4(uint32_t a, uint32_t& r0, uint32_t& r1,
                                      uint32_t& r2, uint32_t& r3) {
    asm volatile("ldmatrix.sync.aligned.m8n8.x4.shared.b16 {%0,%1,%2,%3}, [%4];"
                 : "=r"(r0), "=r"(r1), "=r"(r2), "=r"(r3) : "r"(a));
}
__device__ __forceinline__ void ldsm2(uint32_t a, uint32_t& r0, uint32_t& r1) {
    asm volatile("ldmatrix.sync.aligned.m8n8.x2.shared.b16 {%0,%1}, [%2];"
                 : "=r"(r0), "=r"(r1) : "r"(a));
}
__device__ __forceinline__ void mma_tf32(float& c0, float& c1, float& c2, float& c3,
                                         uint32_t a0, uint32_t a1, uint32_t a2, uint32_t a3,
                                         uint32_t b0, uint32_t b1) {
    asm volatile(
        "mma.sync.aligned.m16n8k8.row.col.f32.tf32.tf32.f32 "
        "{%0,%1,%2,%3}, {%4,%5,%6,%7}, {%8,%9}, {%0,%1,%2,%3};"
        : "+f"(c0), "+f"(c1), "+f"(c2), "+f"(c3)
        : "r"(a0), "r"(a1), "r"(a2), "r"(a3), "r"(b0), "r"(b1));
}
__device__ __forceinline__ void cpasync16(uint32_t saddr, const void* g) {
    asm volatile("cp.async.cg.shared.global [%0], [%1], 16;" :: "r"(saddr), "l"(g));
}
#define CP_COMMIT asm volatile("cp.async.commit_group;")
#define CP_WAIT1  asm volatile("cp.async.wait_group 1;")
#define CP_WAIT0  asm volatile("cp.async.wait_group 0;")

// ---------------------------------------------------------------------------
// Pre-pass: round x to tf32
// ---------------------------------------------------------------------------
__global__ __launch_bounds__(256) void round_x_kernel(const float* __restrict__ x)
{
    size_t i = ((size_t)blockIdx.x * 256 + threadIdx.x) * 4;
    float4 v = *(const float4*)(x + i);
    v.x = tf32r(v.x); v.y = tf32r(v.y); v.z = tf32r(v.z); v.w = tf32r(v.w);
    *(float4*)(g_x + i) = v;
}

// Pre-pass: transpose + round W (1024x1024) into g_wt[which]
__global__ __launch_bounds__(256) void transpose_w_kernel(const float* __restrict__ W,
                                                          int which)
{
    __shared__ float tile[32][33];
    int bx = blockIdx.x * 32, by = blockIdx.y * 32;
    int tx = threadIdx.x & 31, ty = threadIdx.x >> 5;   // 32 x 8
    #pragma unroll
    for (int i = 0; i < 4; i++)
        tile[ty + 8 * i][tx] = W[(size_t)(by + ty + 8 * i) * CC + bx + tx];
    __syncthreads();
    float* dst = g_wt + (size_t)which * CC * CC;
    #pragma unroll
    for (int i = 0; i < 4; i++)
        dst[(size_t)(bx + ty + 8 * i) * CC + by + tx] = tf32r(tile[tx][ty + 8 * i]);
}

// ---------------------------------------------------------------------------
// tf32 GEMM: C(M x 1024) = A(M x 1024) @ W, A row-major, W^T in g_wt[w_sel].
// CTA 256 thr, tile 128x128, warp tile 64x32, k-stage 32, cp.async dbl-buffer.
// mode 0/1: Q/K -> [bn][t][d] (tf32-rounded). mode 2: V -> [bn][d][t] rounded.
// mode 3: final out (plain fp32).
// ---------------------------------------------------------------------------
#define GP 44
#define GEMM_SMEM (4 * 128 * GP * 4)

__global__ __launch_bounds__(256) void gemm_tf32(int a_sel, int w_sel,
                                                 const float* __restrict__ bias,
                                                 float* __restrict__ dst_ext, int mode)
{
    extern __shared__ float sm[];
    float* As = sm;                       // [2][128*GP]
    float* Bs = sm + 2 * 128 * GP;        // [2][128*GP]

    const float* __restrict__ A  = a_sel ? g_attn : g_x;
    const float* __restrict__ BT = g_wt + (size_t)w_sel * CC * CC;

    const int t = threadIdx.x, lane = t & 31, warp = t >> 5;
    const int wm = (warp >> 2) * 64, wn = (warp & 3) * 32;
    const int bm = blockIdx.x * 128, bnc = blockIdx.y * 128;

    const uint32_t sA = smem_u32(As), sB = smem_u32(Bs);

    float acc[4][4][4] = {};

    // stage loader
    auto load_stage = [&](int ks, int buf) {
        int k0 = ks * 32;
        #pragma unroll
        for (int i = 0; i < 4; i++) {
            int lin = t + 256 * i;
            int row = lin >> 3;
            int c4  = (lin & 7) << 2;
            uint32_t so = (uint32_t)((buf * 128 * GP + row * GP + c4) << 2);
            cpasync16(sA + so, A  + (size_t)(bm + row) * CC + k0 + c4);
            cpasync16(sB + so, BT + (size_t)(bnc + row) * CC + k0 + c4);
        }
        CP_COMMIT;
    };

    load_stage(0, 0);
    for (int ks = 0; ks < 32; ks++) {
        int buf = ks & 1;
        if (ks + 1 < 32) { load_stage(ks + 1, (ks + 1) & 1); CP_WAIT1; }
        else             { CP_WAIT0; }
        __syncthreads();

        #pragma unroll
        for (int kk = 0; kk < 4; kk++) {
            uint32_t af[4][4];
            #pragma unroll
            for (int mt = 0; mt < 4; mt++) {
                uint32_t a = sA + (uint32_t)((buf * 128 * GP +
                              (wm + mt * 16 + (lane & 15)) * GP +
                              kk * 8 + ((lane >> 4) << 2)) << 2);
                ldsm4(a, af[mt][0], af[mt][1], af[mt][2], af[mt][3]);
            }
            #pragma unroll
            for (int nt = 0; nt < 4; nt++) {
                uint32_t b0, b1;
                uint32_t a = sB + (uint32_t)((buf * 128 * GP +
                              (wn + nt * 8 + (lane & 7)) * GP +
                              kk * 8 + (((lane >> 3) & 1) << 2)) << 2);
                ldsm2(a, b0, b1);
                #pragma unroll
                for (int mt = 0; mt < 4; mt++)
                    mma_tf32(acc[mt][nt][0], acc[mt][nt][1], acc[mt][nt][2], acc[mt][nt][3],
                             af[mt][0], af[mt][1], af[mt][2], af[mt][3], b0, b1);
            }
        }
        __syncthreads();
    }

    // Epilogue
    #pragma unroll
    for (int mt = 0; mt < 4; mt++) {
        #pragma unroll
        for (int nt = 0; nt < 4; nt++) {
            int r = bm + wm + mt * 16 + (lane >> 2);
            int c = bnc + wn + nt * 8 + ((lane & 3) << 1);
            float bv0 = bias[c], bv1 = bias[c + 1];
            float v0 = acc[mt][nt][0] + bv0, v1 = acc[mt][nt][1] + bv1;
            float v2 = acc[mt][nt][2] + bv0, v3 = acc[mt][nt][3] + bv1;
            if (mode == 3) {
                *(float2*)(dst_ext + (size_t)r * CC + c)       = make_float2(v0, v1);
                *(float2*)(dst_ext + (size_t)(r + 8) * CC + c) = make_float2(v2, v3);
            } else {
                int b = r >> 11, tt = r & 2047;
                int hn = c >> 6, d = c & 63;
                size_t bnix = (size_t)(b * NH + hn);
                if (mode == 2) {
                    g_v[(bnix * DD + d)     * TT + tt]     = tf32r(v0);
                    g_v[(bnix * DD + d + 1) * TT + tt]     = tf32r(v1);
                    g_v[(bnix * DD + d)     * TT + tt + 8] = tf32r(v2);
                    g_v[(bnix * DD + d + 1) * TT + tt + 8] = tf32r(v3);
                } else {
                    float* dst = (mode == 0) ? g_q : g_k;
                    *(float2*)(dst + (bnix * TT + tt) * DD + d) =
                        make_float2(tf32r(v0), tf32r(v1));
                    *(float2*)(dst + (bnix * TT + tt + 8) * DD + d) =
                        make_float2(tf32r(v2), tf32r(v3));
                }
            }
        }
    }
}

// ---------------------------------------------------------------------------
// Two-pass causal attention (tf32 mma).
// Pass 1: QK^T + exp -> row sums only (no stores, no V).
// Pass 2: recompute, normalize by 1/l, single fp32 store of weights,
//         P@V accumulation, O store.  Tail: zero-fill upper tiles.
// Grid (32 qtiles reversed, 64 bn), block 128 (4 warps x 16 q-rows).
// ---------------------------------------------------------------------------
#define AP 68
#define ATTN_SMEM (3 * 64 * AP * 4)

__global__ __launch_bounds__(128) void attn_tf32(float* __restrict__ w_out)
{
    extern __shared__ float sm[];
    float* Qs = sm;               // [64][AP]  (reused as P stage)
    float* Ks = sm + 64 * AP;     // [64][AP]  [tok][d]
    float* Vs = Ks + 64 * AP;     // [64][AP]  [d][tok]

    const int t = threadIdx.x, lane = t & 31, wid = t >> 5;
    const int qb = gridDim.x - 1 - blockIdx.x;   // longest blocks first
    const int bn = blockIdx.y;
    const int q0 = qb * 64;

    const float* __restrict__ Qg = g_q + (size_t)bn * TT * DD;
    const float* __restrict__ Kg = g_k + (size_t)bn * TT * DD;
    const float* __restrict__ Vg = g_v + (size_t)bn * DD * TT;

    // Load Q tile [64][64]
    #pragma unroll
    for (int i = 0; i < 8; i++) {
        int lin = t + 128 * i;
        int row = lin >> 4;
        int c4  = (lin & 15) << 2;
        *(float4*)(Qs + row * AP + c4) = *(const float4*)(Qg + (size_t)(q0 + row) * DD + c4);
    }
    __syncthreads();

    const uint32_t sQ = smem_u32(Qs), sK = smem_u32(Ks), sV = smem_u32(Vs);

    // Q fragments (persistent across both passes): 8 d-steps x 4 regs
    uint32_t qf[8][4];
    #pragma unroll
    for (int ds = 0; ds < 8; ds++) {
        uint32_t a = sQ + (uint32_t)(((wid * 16 + (lane & 15)) * AP +
                          ds * 8 + ((lane >> 4) << 2)) << 2);
        ldsm4(a, qf[ds][0], qf[ds][1], qf[ds][2], qf[ds][3]);
    }

    const int rl = lane >> 2;
    const int cl = (lane & 3) << 1;
    const int rowg0 = q0 + wid * 16 + rl;
    const int rowg1 = rowg0 + 8;
    float* wrow0 = w_out + ((size_t)bn * TT + rowg0) * TT;
    float* wrow1 = w_out + ((size_t)bn * TT + rowg1) * TT;

    // ================= PASS 1: row sums =================
    float l0 = 0.f, l1 = 0.f;
    for (int kt = 0; kt <= qb; kt++) {
        __syncthreads();
        #pragma unroll
        for (int i = 0; i < 8; i++) {
            int lin = t + 128 * i;
            int row = lin >> 4;
            int c4  = (lin & 15) << 2;
            *(float4*)(Ks + row * AP + c4) =
                *(const float4*)(Kg + (size_t)(kt * 64 + row) * DD + c4);
        }
        __syncthreads();

        #pragma unroll
        for (int nt = 0; nt < 8; nt++) {
            float s0 = 0.f, s1 = 0.f, s2 = 0.f, s3 = 0.f;
            #pragma unroll
            for (int dp = 0; dp < 4; dp++) {
                uint32_t b00, b01, b10, b11;
                uint32_t a = sK + (uint32_t)(((nt * 8 + (lane & 7)) * AP +
                                  dp * 16 + ((lane >> 3) << 2)) << 2);
                ldsm4(a, b00, b01, b10, b11);
                mma_tf32(s0, s1, s2, s3, qf[2*dp][0], qf[2*dp][1], qf[2*dp][2], qf[2*dp][3], b00, b01);
                mma_tf32(s0, s1, s2, s3, qf[2*dp+1][0], qf[2*dp+1][1], qf[2*dp+1][2], qf[2*dp+1][3], b10, b11);
            }
            int colg = kt * 64 + nt * 8 + cl;
            float p0 = __expf(s0 * 0.125f);
            float p1 = __expf(s1 * 0.125f);
            float p2 = __expf(s2 * 0.125f);
            float p3 = __expf(s3 * 0.125f);
            if (kt == qb) {
                if (colg     > rowg0) p0 = 0.f;
                if (colg + 1 > rowg0) p1 = 0.f;
                if (colg     > rowg1) p2 = 0.f;
                if (colg + 1 > rowg1) p3 = 0.f;
            }
            l0 += tf32r(p0) + tf32r(p1);
            l1 += tf32r(p2) + tf32r(p3);
        }
    }
    // reduce row sums across the 4 lanes holding each row
    l0 += __shfl_xor_sync(0xffffffffu, l0, 1);
    l0 += __shfl_xor_sync(0xffffffffu, l0, 2);
    l1 += __shfl_xor_sync(0xffffffffu, l1, 1);
    l1 += __shfl_xor_sync(0xffffffffu, l1, 2);
    const float li0 = 1.f / l0, li1 = 1.f / l1;

    // ================= PASS 2: normalized weights + O =================
    float o[8][4] = {};
    for (int kt = 0; kt <= qb; kt++) {
        __syncthreads();
        #pragma unroll
        for (int i = 0; i < 8; i++) {
            int lin = t + 128 * i;
            int row = lin >> 4;
            int c4  = (lin & 15) << 2;
            *(float4*)(Ks + row * AP + c4) =
                *(const float4*)(Kg + (size_t)(kt * 64 + row) * DD + c4);
            *(float4*)(Vs + row * AP + c4) =
                *(const float4*)(Vg + (size_t)row * TT + kt * 64 + c4);
        }
        __syncthreads();

        #pragma unroll
        for (int nt = 0; nt < 8; nt++) {
            float s0 = 0.f, s1 = 0.f, s2 = 0.f, s3 = 0.f;
            #pragma unroll
            for (int dp = 0; dp < 4; dp++) {
                uint32_t b00, b01, b10, b11;
                uint32_t a = sK + (uint32_t)(((nt * 8 + (lane & 7)) * AP +
                                  dp * 16 + ((lane >> 3) << 2)) << 2);
                ldsm4(a, b00, b01, b10, b11);
                mma_tf32(s0, s1, s2, s3, qf[2*dp][0], qf[2*dp][1], qf[2*dp][2], qf[2*dp][3], b00, b01);
                mma_tf32(s0, s1, s2, s3, qf[2*dp+1][0], qf[2*dp+1][1], qf[2*dp+1][2], qf[2*dp+1][3], b10, b11);
            }
            int colg = kt * 64 + nt * 8 + cl;
            float p0 = __expf(s0 * 0.125f);
            float p1 = __expf(s1 * 0.125f);
            float p2 = __expf(s2 * 0.125f);
            float p3 = __expf(s3 * 0.125f);
            if (kt == qb) {
                if (colg     > rowg0) p0 = 0.f;
                if (colg + 1 > rowg0) p1 = 0.f;
                if (colg     > rowg1) p2 = 0.f;
                if (colg + 1 > rowg1) p3 = 0.f;
            }
            // normalized weights (single store, full fp32 precision)
            float w0 = tf32r(p0) * li0, w1 = tf32r(p1) * li0;
            float w2 = tf32r(p2) * li1, w3 = tf32r(p3) * li1;
            *(float2*)(wrow0 + colg) = make_float2(w0, w1);
            *(float2*)(wrow1 + colg) = make_float2(w2, w3);
            // stage tf32-rounded normalized P for the PV mma
            int lr = wid * 16 + rl, lc = nt * 8 + cl;
            *(float2*)(Qs + lr * AP + lc)       = make_float2(tf32r(w0), tf32r(w1));
            *(float2*)(Qs + (lr + 8) * AP + lc) = make_float2(tf32r(w2), tf32r(w3));
        }
        __syncwarp();

        // ---- P fragments ----
        uint32_t pf[8][4];
        #pragma unroll
        for (int ksx = 0; ksx < 8; ksx++) {
            uint32_t a = sQ + (uint32_t)(((wid * 16 + (lane & 15)) * AP +
                              ksx * 8 + ((lane >> 4) << 2)) << 2);
            ldsm4(a, pf[ksx][0], pf[ksx][1], pf[ksx][2], pf[ksx][3]);
        }
        // ---- O += P @ V ----
        #pragma unroll
        for (int nt = 0; nt < 8; nt++) {
            #pragma unroll
            for (int kp = 0; kp < 4; kp++) {
                uint32_t b00, b01, b10, b11;
                uint32_t a = sV + (uint32_t)(((nt * 8 + (lane & 7)) * AP +
                                  kp * 16 + ((lane >> 3) << 2)) << 2);
                ldsm4(a, b00, b01, b10, b11);
                mma_tf32(o[nt][0], o[nt][1], o[nt][2], o[nt][3],
                         pf[2*kp][0], pf[2*kp][1], pf[2*kp][2], pf[2*kp][3], b00, b01);
                mma_tf32(o[nt][0], o[nt][1], o[nt][2], o[nt][3],
                         pf[2*kp+1][0], pf[2*kp+1][1], pf[2*kp+1][2], pf[2*kp+1][3], b10, b11);
            }
        }
    }

    // store O (already normalized, tf32-rounded) in [b][t][hn*64+d]
    int b = bn >> 4, hn = bn & 15;
    float* Og0 = g_attn + ((size_t)b * TT + rowg0) * CC + hn * DD;
    float* Og1 = g_attn + ((size_t)b * TT + rowg1) * CC + hn * DD;
    #pragma unroll
    for (int nt = 0; nt < 8; nt++) {
        *(float2*)(Og0 + nt * 8 + cl) =
            make_float2(tf32r(o[nt][0]), tf32r(o[nt][1]));
        *(float2*)(Og1 + nt * 8 + cl) =
            make_float2(tf32r(o[nt][2]), tf32r(o[nt][3]));
    }

    // Zero-fill strictly-upper tiles (float4 stores, 128 threads)
    {
        const float4 z = make_float4(0.f, 0.f, 0.f, 0.f);
        const int row = t >> 1;                  // 0..63
        const int cq  = (t & 1) << 5;            // 0 or 32
        float* wr = w_out + ((size_t)bn * TT + q0 + row) * TT;
        for (int kt = qb + 1; kt < TT / 64; kt++) {
            float* p = wr + kt * 64 + cq;
            #pragma unroll
            for (int j = 0; j < 8; j++)
                *(float4*)(p + 4 * j) = z;
        }
    }
}

// ---------------------------------------------------------------------------
extern "C" void kernel_launch(void* const* d_in, const int* in_sizes, int n_in,
                              void* d_out, int out_size)
{
    const float* x  = (const float*)d_in[0];
    const float* Wq = (const float*)d_in[1];
    const float* bq = (const float*)d_in[2];
    const float* Wk = (const float*)d_in[3];
    const float* bk = (const float*)d_in[4];
    const float* Wv = (const float*)d_in[5];
    const float* bv = (const float*)d_in[6];
    const float* Wo = (const float*)d_in[7];
    const float* bo = (const float*)d_in[8];
    float* out = (float*)d_out;
    float* w_out = out + OUT_ELEMS;

    cudaFuncSetAttribute(gemm_tf32, cudaFuncAttributeMaxDynamicSharedMemorySize, GEMM_SMEM);
    cudaFuncSetAttribute(attn_tf32, cudaFuncAttributeMaxDynamicSharedMemorySize, ATTN_SMEM);

    // Pre-round / transpose
    round_x_kernel<<<(MROWS * CC) / (256 * 4), 256>>>(x);
    dim3 tg(32, 32);
    transpose_w_kernel<<<tg, 256>>>(Wq, 0);
    transpose_w_kernel<<<tg, 256>>>(Wk, 1);
    transpose_w_kernel<<<tg, 256>>>(Wv, 2);
    transpose_w_kernel<<<tg, 256>>>(Wo, 3);

    dim3 gg(MROWS / 128, CC / 128);
    gemm_tf32<<<gg, 256, GEMM_SMEM>>>(0, 0, bq, nullptr, 0);
    gemm_tf32<<<gg, 256, GEMM_SMEM>>>(0, 1, bk, nullptr, 1);
    gemm_tf32<<<gg, 256, GEMM_SMEM>>>(0, 2, bv, nullptr, 2);

    dim3 ag(TT / 64, BB * NH);
    attn_tf32<<<ag, 128, ATTN_SMEM>>>(w_out);

    gemm_tf32<<<gg, 256, GEMM_SMEM>>>(1, 3, bo, out, 3);
}